// round 15
// baseline (speedup 1.0000x reference)
#include <cuda_runtime.h>
#include <cuda_bf16.h>
#include <cuda_fp16.h>
#include <math.h>

// Problem dims
#define B_   128
#define T_   512
#define E_   256
#define H_   512
#define G3   1536   // 3H per direction
#define GT   3072   // both directions stacked

// Recurrence: 2 dirs x 64 CTAs, each owns 8 GRU units (all 3 gates), full K=512
#define NDIR       2
#define CTAS_DIR   64
#define NCTA_REC   (NDIR * CTAS_DIR)    // 128
#define UNITS      8
#define REC_THREADS 512

// ---------------- scratch (device globals; no allocation allowed) ----------------
__device__ float  g_xpT[(size_t)T_ * GT * B_];     // xpT[t][g][b]
__device__ __half g_hp[NDIR * B_ * H_];            // h fp16 [dir][b][j] (broadcast)
__device__ float  g_hf[NDIR * H_ * B_];            // final h fp32 [dir][j][b] (for fc)
__device__ unsigned g_bc[NDIR];
__device__ unsigned g_bg[NDIR];
__device__ unsigned g_ibc;
__device__ unsigned g_ibg;

// ---------------- PTX helpers ----------------
__device__ __forceinline__ unsigned smem_u32(const void* p) {
    unsigned a;
    asm("{ .reg .u64 t; cvta.to.shared.u64 t, %1; cvt.u32.u64 %0, t; }" : "=r"(a) : "l"(p));
    return a;
}
__device__ __forceinline__ void ldsm4(unsigned* r, unsigned addr) {
    asm volatile("ldmatrix.sync.aligned.m8n8.x4.shared.b16 {%0,%1,%2,%3}, [%4];"
        : "=r"(r[0]), "=r"(r[1]), "=r"(r[2]), "=r"(r[3]) : "r"(addr));
}
__device__ __forceinline__ void mma16816(float* d, const unsigned* a,
                                         unsigned b0, unsigned b1) {
    asm volatile(
        "mma.sync.aligned.m16n8k16.row.col.f32.f16.f16.f32 "
        "{%0,%1,%2,%3}, {%4,%5,%6,%7}, {%8,%9}, {%0,%1,%2,%3};"
        : "+f"(d[0]), "+f"(d[1]), "+f"(d[2]), "+f"(d[3])
        : "r"(a[0]), "r"(a[1]), "r"(a[2]), "r"(a[3]), "r"(b0), "r"(b1));
}
__device__ __forceinline__ void cp16(unsigned dst, const void* src) {
    asm volatile("cp.async.cg.shared.global [%0], [%1], 16;"
        :: "r"(dst), "l"(src) : "memory");
}
#define CP_COMMIT() asm volatile("cp.async.commit_group;" ::: "memory")
template <int N>
__device__ __forceinline__ void cp_wait() {
    asm volatile("cp.async.wait_group %0;" :: "n"(N) : "memory");
}
#define CP_WAIT_ALL() asm volatile("cp.async.commit_group;\n cp.async.wait_group 0;" ::: "memory")

// swizzled byte offset, 1024B rows (512 fp16/row) — rec tiles
__device__ __forceinline__ int sw_off(int row, int kbyte) {
    return row * 1024 + (kbyte ^ ((row & 7) << 4));
}
// swizzled byte offset, 512B rows (256 fp16/row) — proj tiles
__device__ __forceinline__ int sw512(int row, int kbyte) {
    return row * 512 + (kbyte ^ ((row & 7) << 4));
}

// =================================================================================
// dummy kernels: shift ncu's -s 5 -c 1 capture window onto rec_kernel
// =================================================================================
__global__ void dummy_kernel() {}

// =================================================================================
// Phase 1: input projection, fp16 HMMA with W-resident t-loop (R14, measured-good)
// =================================================================================
#define PJ_W   0
#define PJ_E   65536
#define PJ_TOK 131072
#define PJ_END 131584
#define TCH    16      // timesteps per CTA

__global__ void __launch_bounds__(256) proj_kernel(
    const int* __restrict__ inputs, const float* __restrict__ emb,
    const float* __restrict__ Wf, const float* __restrict__ Wb,
    const float* __restrict__ bf, const float* __restrict__ bb)
{
    extern __shared__ char psm[];
    const unsigned sb = smem_u32(psm);
    int* toks = reinterpret_cast<int*>(psm + PJ_TOK);

    const int gtile = blockIdx.x;          // 0..23
    const int t0    = blockIdx.y * TCH;    // 0..511 step 16
    const int tid   = threadIdx.x;
    const int wid   = tid >> 5;
    const int lane  = tid & 31;

    const int g0  = gtile * 128;
    const int isB = (g0 >= G3);
    const float* W    = isB ? Wb : Wf;
    const float* bias = isB ? bb : bf;
    const int    gl0  = g0 - (isB ? G3 : 0);

    // ---- one-time: W tile -> fp16 swizzled SMEM
    for (int i = tid; i < 128 * 32; i += 256) {
        int r = i >> 5, kq = i & 31;
        const float* src = &W[(size_t)(gl0 + r) * E_ + kq * 8];
        float4 v0 = *reinterpret_cast<const float4*>(src);
        float4 v1 = *reinterpret_cast<const float4*>(src + 4);
        __half2 p0 = __floats2half2_rn(v0.x, v0.y);
        __half2 p1 = __floats2half2_rn(v0.z, v0.w);
        __half2 p2 = __floats2half2_rn(v1.x, v1.y);
        __half2 p3 = __floats2half2_rn(v1.z, v1.w);
        uint4 u;
        u.x = *reinterpret_cast<unsigned*>(&p0);
        u.y = *reinterpret_cast<unsigned*>(&p1);
        u.z = *reinterpret_cast<unsigned*>(&p2);
        u.w = *reinterpret_cast<unsigned*>(&p3);
        *reinterpret_cast<uint4*>(psm + PJ_W + sw512(r, kq * 16)) = u;
    }

    const int wm = wid & 3;
    const int wn = wid >> 2;
    const int lrow = lane & 15;
    const int lkb  = (lane >> 4) * 16;

    unsigned a_base[2]; int a_xor[2];
    #pragma unroll
    for (int mi = 0; mi < 2; mi++) {
        int arow = wm*32 + mi*16 + lrow;
        a_base[mi] = sb + PJ_W + arow * 512;
        a_xor[mi]  = (arow & 7) << 4;
    }
    unsigned b_base[4]; int b_xor[4];
    #pragma unroll
    for (int nt = 0; nt < 4; nt++) {
        int brow = wn*64 + nt*16 + lrow;
        b_base[nt] = sb + PJ_E + brow * 512;
        b_xor[nt]  = (brow & 7) << 4;
    }

    float bv[2][2];
    #pragma unroll
    for (int mi = 0; mi < 2; mi++) {
        int r = wm*32 + mi*16 + (lane >> 2);
        bv[mi][0] = bias[gl0 + r];
        bv[mi][1] = bias[gl0 + r + 8];
    }

    for (int tt = 0; tt < TCH; tt++) {
        const int t = t0 + tt;
        if (tid < 128) toks[tid] = inputs[tid * T_ + t];
        __syncthreads();

        for (int i = tid; i < 128 * 32; i += 256) {
            int b = i >> 5, kq = i & 31;
            const float* src = &emb[(size_t)toks[b] * E_ + kq * 8];
            float4 v0 = *reinterpret_cast<const float4*>(src);
            float4 v1 = *reinterpret_cast<const float4*>(src + 4);
            __half2 p0 = __floats2half2_rn(v0.x, v0.y);
            __half2 p1 = __floats2half2_rn(v0.z, v0.w);
            __half2 p2 = __floats2half2_rn(v1.x, v1.y);
            __half2 p3 = __floats2half2_rn(v1.z, v1.w);
            uint4 u;
            u.x = *reinterpret_cast<unsigned*>(&p0);
            u.y = *reinterpret_cast<unsigned*>(&p1);
            u.z = *reinterpret_cast<unsigned*>(&p2);
            u.w = *reinterpret_cast<unsigned*>(&p3);
            *reinterpret_cast<uint4*>(psm + PJ_E + sw512(b, kq * 16)) = u;
        }
        __syncthreads();

        float d[2][8][4];
        #pragma unroll
        for (int mi = 0; mi < 2; mi++)
            #pragma unroll
            for (int n8 = 0; n8 < 8; n8++)
                #pragma unroll
                for (int q = 0; q < 4; q++) d[mi][n8][q] = 0.f;

        #pragma unroll
        for (int ks = 0; ks < 16; ks++) {
            const int kb = ks * 32 + lkb;
            unsigned a0[4], a1[4];
            ldsm4(a0, a_base[0] + (kb ^ a_xor[0]));
            ldsm4(a1, a_base[1] + (kb ^ a_xor[1]));
            #pragma unroll
            for (int nt = 0; nt < 4; nt++) {
                unsigned bb4[4];
                ldsm4(bb4, b_base[nt] + (kb ^ b_xor[nt]));
                mma16816(d[0][2*nt],   a0, bb4[0], bb4[2]);
                mma16816(d[0][2*nt+1], a0, bb4[1], bb4[3]);
                mma16816(d[1][2*nt],   a1, bb4[0], bb4[2]);
                mma16816(d[1][2*nt+1], a1, bb4[1], bb4[3]);
            }
        }

        {
            const int c0 = (lane & 3) * 2;
            #pragma unroll
            for (int mi = 0; mi < 2; mi++) {
                int r0 = wm*32 + mi*16 + (lane >> 2);
                #pragma unroll
                for (int n8 = 0; n8 < 8; n8++) {
                    int col = wn*64 + n8*8 + c0;
                    float* dst = &g_xpT[((size_t)t * GT + g0 + r0) * B_ + col];
                    *reinterpret_cast<float2*>(dst) =
                        make_float2(d[mi][n8][0] + bv[mi][0], d[mi][n8][1] + bv[mi][0]);
                    float* dst8 = &g_xpT[((size_t)t * GT + g0 + r0 + 8) * B_ + col];
                    *reinterpret_cast<float2*>(dst8) =
                        make_float2(d[mi][n8][2] + bv[mi][1], d[mi][n8][3] + bv[mi][1]);
                }
            }
        }
        __syncthreads();
    }
}

// =================================================================================
// Phase 2: persistent recurrence — chunked cp.async pipeline under the MMA.
// 512 threads. CTA (dir, c64) owns units j0..j0+7 (24 gate rows + 8 pad).
// =================================================================================
#define SO_W   0           // 32 x 1024B = 32 KB (rows 24..31 zero padding)
#define SO_H   32768       // 128 x 1024B = 128 KB
#define SO_S   163840      // 32 x 128 fp32 = 16 KB (D tile)
#define SO_END 180224

__global__ void __launch_bounds__(REC_THREADS, 1) rec_kernel(
    const float* __restrict__ Whf, const float* __restrict__ Whb,
    const float* __restrict__ bhf, const float* __restrict__ bhb)
{
    extern __shared__ char smem[];
    const unsigned sb = smem_u32(smem);
    float* S = reinterpret_cast<float*>(smem + SO_S);
    const int tid  = threadIdx.x;
    const int wid  = tid >> 5;     // 0..15
    const int lane = tid & 31;

    const int cta = blockIdx.x;        // 0..127
    const int dir = cta & 1;
    const int c64 = cta >> 1;          // 0..63
    const int j0  = c64 * UNITS;
    const float* Wh = dir ? Whb : Whf;
    const float* bh = dir ? bhb : bhf;

    // ---- zero W SMEM (incl. pad rows), fill 24 rows fp16 swizzled
    for (int i = tid; i < 32768/16; i += REC_THREADS)
        *reinterpret_cast<uint4*>(smem + SO_W + i*16) = make_uint4(0,0,0,0);
    __syncthreads();
    for (int i = tid; i < 24*512; i += REC_THREADS) {
        int r = i >> 9, k = i & 511;
        int gate = r >> 3, u = r & 7;
        float w = Wh[(size_t)(gate*H_ + j0 + u) * H_ + k];
        *reinterpret_cast<__half*>(smem + SO_W + sw_off(r, k*2)) = __float2half_rn(w);
    }

    // ---- zero h broadcast buffer (grid-strided)
    {
        const int gt = cta * REC_THREADS + tid;
        const int nthr = NCTA_REC * REC_THREADS;
        unsigned long long* hp4 = reinterpret_cast<unsigned long long*>(g_hp);
        for (int i = gt; i < NDIR*B_*H_/4; i += nthr) hp4[i] = 0ull;
    }
    __threadfence();
    __syncthreads();
    if (tid == 0) {
        volatile unsigned* gp = &g_ibg;
        unsigned old = *gp;
        __threadfence();
        if (atomicAdd(&g_ibc, 1u) == NCTA_REC - 1) {
            atomicExch(&g_ibc, 0u); __threadfence(); *gp = old + 1;
        } else { while (*gp == old) {} }
    }
    __syncthreads();

    // warp tiling (16 warps): mi = wid&1 (m16 tile), ni = wid>>1 (n16 group 0..7)
    const int mi = wid & 1;
    const int ni = wid >> 1;
    const int lrow = lane & 15;
    const int lkb  = (lane >> 4) * 16;

    const unsigned a_base = sb + SO_W + (mi*16 + lrow) * 1024;
    const int      a_xor  = ((mi*16 + lrow) & 7) << 4;
    const unsigned b_base = sb + SO_H + (ni*16 + lrow) * 1024;
    const int      b_xor  = ((ni*16 + lrow) & 7) << 4;

    // gating thread mapping: (b, 2 units)
    const int gb = tid & 127;
    const int uh = tid >> 7;           // 0..3 -> units uh*2, uh*2+1
    float hreg[2] = {0.f, 0.f};

    // loop-invariant bias values
    float bhv[2][3];
    #pragma unroll
    for (int q = 0; q < 2; q++)
        #pragma unroll
        for (int gate = 0; gate < 3; gate++)
            bhv[q][gate] = bh[gate*H_ + j0 + uh*2 + q];

    // prefetch xg for t=0
    float xgn[6];
    {
        const int te0 = dir ? (T_ - 1) : 0;
        #pragma unroll
        for (int q = 0; q < 2; q++)
            #pragma unroll
            for (int gate = 0; gate < 3; gate++)
                xgn[q*3 + gate] = __ldcg(&g_xpT[((size_t)te0 * GT + dir*G3
                                        + gate*H_ + j0 + uh*2 + q) * B_ + gb]);
    }

    volatile unsigned* genp = &g_bg[dir];
    unsigned* cntp = &g_bc[dir];
    const __half* hsrc = &g_hp[(size_t)(dir*B_) * H_];

    for (int t = 0; t < T_; t++) {
        // ---- issue all 4 k-chunk cp.async groups up front (32KB each)
        #pragma unroll
        for (int c = 0; c < 4; c++) {
            #pragma unroll
            for (int i = 0; i < 4; i++) {
                int idx = tid + i * REC_THREADS;      // 0..2047
                int b = idx >> 4, kq = idx & 15;
                int k8 = c * 16 + kq;                 // 8-half group 0..63
                cp16(sb + SO_H + sw_off(b, k8*16), hsrc + (size_t)b * H_ + k8*8);
            }
            CP_COMMIT();
        }

        // ---- pipelined mainloop: MMA chunk c while chunks c+1.. are in flight
        float d[2][4];
        #pragma unroll
        for (int g8 = 0; g8 < 2; g8++)
            #pragma unroll
            for (int q = 0; q < 4; q++) d[g8][q] = 0.f;

        #pragma unroll
        for (int c = 0; c < 4; c++) {
            switch (c) {
                case 0: cp_wait<3>(); break;
                case 1: cp_wait<2>(); break;
                case 2: cp_wait<1>(); break;
                default: cp_wait<0>(); break;
            }
            __syncthreads();
            #pragma unroll
            for (int ks8 = 0; ks8 < 8; ks8++) {
                const int kb = (c * 8 + ks8) * 32 + lkb;
                unsigned a[4], bb4[4];
                ldsm4(a,   a_base + (kb ^ a_xor));
                ldsm4(bb4, b_base + (kb ^ b_xor));
                mma16816(d[0], a, bb4[0], bb4[2]);
                mma16816(d[1], a, bb4[1], bb4[3]);
            }
        }

        // ---- epilogue: fragments -> S[32][128] fp32
        {
            const int r0 = mi*16 + (lane >> 2);
            const int c0 = (lane & 3) * 2;
            #pragma unroll
            for (int g8 = 0; g8 < 2; g8++) {
                int col = ni*16 + g8*8 + c0;
                *reinterpret_cast<float2*>(&S[r0 * 128 + col]) =
                    make_float2(d[g8][0], d[g8][1]);
                *reinterpret_cast<float2*>(&S[(r0 + 8) * 128 + col]) =
                    make_float2(d[g8][2], d[g8][3]);
            }
        }
        __syncthreads();

        // ---- gating: thread owns units uh*2, uh*2+1 for batch gb
        __half hnew16[2];
        #pragma unroll
        for (int q = 0; q < 2; q++) {
            int u = uh*2 + q;
            float hg[3];
            #pragma unroll
            for (int gate = 0; gate < 3; gate++)
                hg[gate] = S[(gate*8 + u) * 128 + gb] + bhv[q][gate];
            float r = 1.f / (1.f + __expf(-(xgn[q*3+0] + hg[0])));
            float z = 1.f / (1.f + __expf(-(xgn[q*3+1] + hg[1])));
            float n = tanhf(xgn[q*3+2] + r * hg[2]);
            float hnew = (1.f - z) * n + z * hreg[q];
            hreg[q] = hnew;
            hnew16[q] = __float2half_rn(hnew);
        }
        __stcg(reinterpret_cast<unsigned*>(
                   &g_hp[(size_t)(dir*B_ + gb) * H_ + j0 + uh*2]),
               *reinterpret_cast<unsigned*>(hnew16));

        // ---- barrier with xg-prefetch overlapped into the wait
        __threadfence();
        __syncthreads();
        unsigned oldgen = 0;
        if (tid == 0) {
            oldgen = *genp;
            if (atomicAdd(cntp, 1u) == CTAS_DIR - 1) {
                atomicExch(cntp, 0u);
                __threadfence();
                *genp = oldgen + 1;
            }
        }
        if (t + 1 < T_) {
            const int ten = dir ? (T_ - 2 - t) : (t + 1);
            #pragma unroll
            for (int q = 0; q < 2; q++)
                #pragma unroll
                for (int gate = 0; gate < 3; gate++)
                    xgn[q*3 + gate] = __ldcg(&g_xpT[((size_t)ten * GT + dir*G3
                                            + gate*H_ + j0 + uh*2 + q) * B_ + gb]);
        }
        if (tid == 0) { while (*genp == oldgen) {} }
        __syncthreads();
    }

    // final h fp32 for fc
    #pragma unroll
    for (int q = 0; q < 2; q++)
        g_hf[(size_t)(dir*H_ + j0 + uh*2 + q) * B_ + gb] = hreg[q];
}

// =================================================================================
// Phase 3: final FC + sigmoid
// =================================================================================
__global__ void fc_kernel(const float* __restrict__ fcw,
                          const float* __restrict__ fcb,
                          float* __restrict__ out)
{
    int b = threadIdx.x;   // 128 threads
    float s = 0.f;
    for (int j = 0; j < H_; j++)
        s = fmaf(g_hf[(0*H_ + j) * B_ + b], fcw[j], s);
    for (int j = 0; j < H_; j++)
        s = fmaf(g_hf[(1*H_ + j) * B_ + b], fcw[H_ + j], s);
    out[b] = 1.f / (1.f + __expf(-(s + fcb[0])));
}

// =================================================================================
extern "C" void kernel_launch(void* const* d_in, const int* in_sizes, int n_in,
                              void* d_out, int out_size)
{
    const int*   inputs = (const int*)  d_in[0];
    const float* emb    = (const float*)d_in[1];
    const float* Wihf   = (const float*)d_in[2];
    const float* Whhf   = (const float*)d_in[3];
    const float* bihf   = (const float*)d_in[4];
    const float* bhhf   = (const float*)d_in[5];
    const float* Wihb   = (const float*)d_in[6];
    const float* Whhb   = (const float*)d_in[7];
    const float* bihb   = (const float*)d_in[8];
    const float* bhhb   = (const float*)d_in[9];
    const float* fcw    = (const float*)d_in[10];
    const float* fcb    = (const float*)d_in[11];
    float* out = (float*)d_out;

    cudaFuncSetAttribute(proj_kernel,
                         cudaFuncAttributeMaxDynamicSharedMemorySize, PJ_END);
    cudaFuncSetAttribute(rec_kernel,
                         cudaFuncAttributeMaxDynamicSharedMemorySize, SO_END);

    // 2 dummies: puts rec_kernel at ncu capture index 5
    dummy_kernel<<<1, 32>>>();
    dummy_kernel<<<1, 32>>>();

    proj_kernel<<<dim3(24, 32), 256, PJ_END>>>(inputs, emb, Wihf, Wihb, bihf, bihb);
    rec_kernel<<<NCTA_REC, REC_THREADS, SO_END>>>(Whhf, Whhb, bhhf, bhhb);
    fc_kernel<<<1, B_>>>(fcw, fcb, out);

    (void)in_sizes; (void)n_in; (void)out_size;
}

// round 16
// speedup vs baseline: 1.1371x; 1.1371x over previous
#include <cuda_runtime.h>
#include <cuda_bf16.h>
#include <cuda_fp16.h>
#include <math.h>

// Problem dims
#define B_   128
#define T_   512
#define E_   256
#define H_   512
#define G3   1536   // 3H per direction
#define GT   3072   // both directions stacked

// Recurrence: 2 dirs x 64 CTAs, each owns 8 GRU units (all 3 gates), full K=512
#define NDIR       2
#define CTAS_DIR   64
#define NCTA_REC   (NDIR * CTAS_DIR)    // 128
#define UNITS      8
#define REC_THREADS 512

// ---------------- scratch (device globals; no allocation allowed) ----------------
__device__ float  g_xpT[(size_t)T_ * GT * B_];     // xpT[t][g][b]
__device__ __half g_hp[NDIR * B_ * H_];            // h fp16 [dir][b][j] (broadcast)
__device__ float  g_hf[NDIR * H_ * B_];            // final h fp32 [dir][j][b] (for fc)
__device__ unsigned g_flag[NDIR * CTAS_DIR * 32];  // step flags, 128B-strided
__device__ unsigned g_ibc;
__device__ unsigned g_ibg;

// ---------------- PTX helpers ----------------
__device__ __forceinline__ unsigned smem_u32(const void* p) {
    unsigned a;
    asm("{ .reg .u64 t; cvta.to.shared.u64 t, %1; cvt.u32.u64 %0, t; }" : "=r"(a) : "l"(p));
    return a;
}
__device__ __forceinline__ void ldsm4(unsigned* r, unsigned addr) {
    asm volatile("ldmatrix.sync.aligned.m8n8.x4.shared.b16 {%0,%1,%2,%3}, [%4];"
        : "=r"(r[0]), "=r"(r[1]), "=r"(r[2]), "=r"(r[3]) : "r"(addr));
}
__device__ __forceinline__ void mma16816(float* d, const unsigned* a,
                                         unsigned b0, unsigned b1) {
    asm volatile(
        "mma.sync.aligned.m16n8k16.row.col.f32.f16.f16.f32 "
        "{%0,%1,%2,%3}, {%4,%5,%6,%7}, {%8,%9}, {%0,%1,%2,%3};"
        : "+f"(d[0]), "+f"(d[1]), "+f"(d[2]), "+f"(d[3])
        : "r"(a[0]), "r"(a[1]), "r"(a[2]), "r"(a[3]), "r"(b0), "r"(b1));
}
__device__ __forceinline__ void cp16(unsigned dst, const void* src) {
    asm volatile("cp.async.cg.shared.global [%0], [%1], 16;"
        :: "r"(dst), "l"(src) : "memory");
}
#define CP_WAIT_ALL() asm volatile("cp.async.commit_group;\n cp.async.wait_group 0;" ::: "memory")

// swizzled byte offset, 1024B rows (512 fp16/row) — rec tiles
__device__ __forceinline__ int sw_off(int row, int kbyte) {
    return row * 1024 + (kbyte ^ ((row & 7) << 4));
}
// swizzled byte offset, 512B rows (256 fp16/row) — proj tiles
__device__ __forceinline__ int sw512(int row, int kbyte) {
    return row * 512 + (kbyte ^ ((row & 7) << 4));
}

// =================================================================================
// dummy kernels: shift ncu's -s 5 -c 1 capture window onto rec_kernel
// =================================================================================
__global__ void dummy_kernel() {}

// =================================================================================
// Phase 1: input projection, fp16 HMMA with W-resident t-loop (measured-good)
// =================================================================================
#define PJ_W   0
#define PJ_E   65536
#define PJ_TOK 131072
#define PJ_END 131584
#define TCH    16      // timesteps per CTA

__global__ void __launch_bounds__(256) proj_kernel(
    const int* __restrict__ inputs, const float* __restrict__ emb,
    const float* __restrict__ Wf, const float* __restrict__ Wb,
    const float* __restrict__ bf, const float* __restrict__ bb)
{
    extern __shared__ char psm[];
    const unsigned sb = smem_u32(psm);
    int* toks = reinterpret_cast<int*>(psm + PJ_TOK);

    const int gtile = blockIdx.x;          // 0..23
    const int t0    = blockIdx.y * TCH;    // 0..511 step 16
    const int tid   = threadIdx.x;
    const int wid   = tid >> 5;
    const int lane  = tid & 31;

    const int g0  = gtile * 128;
    const int isB = (g0 >= G3);
    const float* W    = isB ? Wb : Wf;
    const float* bias = isB ? bb : bf;
    const int    gl0  = g0 - (isB ? G3 : 0);

    // ---- one-time: W tile -> fp16 swizzled SMEM
    for (int i = tid; i < 128 * 32; i += 256) {
        int r = i >> 5, kq = i & 31;
        const float* src = &W[(size_t)(gl0 + r) * E_ + kq * 8];
        float4 v0 = *reinterpret_cast<const float4*>(src);
        float4 v1 = *reinterpret_cast<const float4*>(src + 4);
        __half2 p0 = __floats2half2_rn(v0.x, v0.y);
        __half2 p1 = __floats2half2_rn(v0.z, v0.w);
        __half2 p2 = __floats2half2_rn(v1.x, v1.y);
        __half2 p3 = __floats2half2_rn(v1.z, v1.w);
        uint4 u;
        u.x = *reinterpret_cast<unsigned*>(&p0);
        u.y = *reinterpret_cast<unsigned*>(&p1);
        u.z = *reinterpret_cast<unsigned*>(&p2);
        u.w = *reinterpret_cast<unsigned*>(&p3);
        *reinterpret_cast<uint4*>(psm + PJ_W + sw512(r, kq * 16)) = u;
    }

    const int wm = wid & 3;
    const int wn = wid >> 2;
    const int lrow = lane & 15;
    const int lkb  = (lane >> 4) * 16;

    unsigned a_base[2]; int a_xor[2];
    #pragma unroll
    for (int mi = 0; mi < 2; mi++) {
        int arow = wm*32 + mi*16 + lrow;
        a_base[mi] = sb + PJ_W + arow * 512;
        a_xor[mi]  = (arow & 7) << 4;
    }
    unsigned b_base[4]; int b_xor[4];
    #pragma unroll
    for (int nt = 0; nt < 4; nt++) {
        int brow = wn*64 + nt*16 + lrow;
        b_base[nt] = sb + PJ_E + brow * 512;
        b_xor[nt]  = (brow & 7) << 4;
    }

    float bv[2][2];
    #pragma unroll
    for (int mi = 0; mi < 2; mi++) {
        int r = wm*32 + mi*16 + (lane >> 2);
        bv[mi][0] = bias[gl0 + r];
        bv[mi][1] = bias[gl0 + r + 8];
    }

    for (int tt = 0; tt < TCH; tt++) {
        const int t = t0 + tt;
        if (tid < 128) toks[tid] = inputs[tid * T_ + t];
        __syncthreads();

        for (int i = tid; i < 128 * 32; i += 256) {
            int b = i >> 5, kq = i & 31;
            const float* src = &emb[(size_t)toks[b] * E_ + kq * 8];
            float4 v0 = *reinterpret_cast<const float4*>(src);
            float4 v1 = *reinterpret_cast<const float4*>(src + 4);
            __half2 p0 = __floats2half2_rn(v0.x, v0.y);
            __half2 p1 = __floats2half2_rn(v0.z, v0.w);
            __half2 p2 = __floats2half2_rn(v1.x, v1.y);
            __half2 p3 = __floats2half2_rn(v1.z, v1.w);
            uint4 u;
            u.x = *reinterpret_cast<unsigned*>(&p0);
            u.y = *reinterpret_cast<unsigned*>(&p1);
            u.z = *reinterpret_cast<unsigned*>(&p2);
            u.w = *reinterpret_cast<unsigned*>(&p3);
            *reinterpret_cast<uint4*>(psm + PJ_E + sw512(b, kq * 16)) = u;
        }
        __syncthreads();

        float d[2][8][4];
        #pragma unroll
        for (int mi = 0; mi < 2; mi++)
            #pragma unroll
            for (int n8 = 0; n8 < 8; n8++)
                #pragma unroll
                for (int q = 0; q < 4; q++) d[mi][n8][q] = 0.f;

        #pragma unroll
        for (int ks = 0; ks < 16; ks++) {
            const int kb = ks * 32 + lkb;
            unsigned a0[4], a1[4];
            ldsm4(a0, a_base[0] + (kb ^ a_xor[0]));
            ldsm4(a1, a_base[1] + (kb ^ a_xor[1]));
            #pragma unroll
            for (int nt = 0; nt < 4; nt++) {
                unsigned bb4[4];
                ldsm4(bb4, b_base[nt] + (kb ^ b_xor[nt]));
                mma16816(d[0][2*nt],   a0, bb4[0], bb4[2]);
                mma16816(d[0][2*nt+1], a0, bb4[1], bb4[3]);
                mma16816(d[1][2*nt],   a1, bb4[0], bb4[2]);
                mma16816(d[1][2*nt+1], a1, bb4[1], bb4[3]);
            }
        }

        {
            const int c0 = (lane & 3) * 2;
            #pragma unroll
            for (int mi = 0; mi < 2; mi++) {
                int r0 = wm*32 + mi*16 + (lane >> 2);
                #pragma unroll
                for (int n8 = 0; n8 < 8; n8++) {
                    int col = wn*64 + n8*8 + c0;
                    float* dst = &g_xpT[((size_t)t * GT + g0 + r0) * B_ + col];
                    *reinterpret_cast<float2*>(dst) =
                        make_float2(d[mi][n8][0] + bv[mi][0], d[mi][n8][1] + bv[mi][0]);
                    float* dst8 = &g_xpT[((size_t)t * GT + g0 + r0 + 8) * B_ + col];
                    *reinterpret_cast<float2*>(dst8) =
                        make_float2(d[mi][n8][2] + bv[mi][1], d[mi][n8][3] + bv[mi][1]);
                }
            }
        }
        __syncthreads();
    }
}

// =================================================================================
// Phase 2: persistent recurrence — flag-array barrier (no atomic chain).
// 512 threads. CTA (dir, c64) owns units j0..j0+7 (24 gate rows + 8 pad).
// =================================================================================
#define SO_W   0           // 32 x 1024B = 32 KB (rows 24..31 zero padding)
#define SO_H   32768       // 128 x 1024B = 128 KB
#define SO_S   163840      // 32 x 128 fp32 = 16 KB (D tile)
#define SO_END 180224

__global__ void __launch_bounds__(REC_THREADS, 1) rec_kernel(
    const float* __restrict__ Whf, const float* __restrict__ Whb,
    const float* __restrict__ bhf, const float* __restrict__ bhb)
{
    extern __shared__ char smem[];
    const unsigned sb = smem_u32(smem);
    float* S = reinterpret_cast<float*>(smem + SO_S);
    const int tid  = threadIdx.x;
    const int wid  = tid >> 5;     // 0..15
    const int lane = tid & 31;

    const int cta = blockIdx.x;        // 0..127
    const int dir = cta & 1;
    const int c64 = cta >> 1;          // 0..63
    const int j0  = c64 * UNITS;
    const float* Wh = dir ? Whb : Whf;
    const float* bh = dir ? bhb : bhf;

    // ---- zero W SMEM (incl. pad rows), fill 24 rows fp16 swizzled
    for (int i = tid; i < 32768/16; i += REC_THREADS)
        *reinterpret_cast<uint4*>(smem + SO_W + i*16) = make_uint4(0,0,0,0);
    __syncthreads();
    for (int i = tid; i < 24*512; i += REC_THREADS) {
        int r = i >> 9, k = i & 511;
        int gate = r >> 3, u = r & 7;
        float w = Wh[(size_t)(gate*H_ + j0 + u) * H_ + k];
        *reinterpret_cast<__half*>(smem + SO_W + sw_off(r, k*2)) = __float2half_rn(w);
    }

    // ---- zero h broadcast buffer and step flags (grid-strided)
    {
        const int gt = cta * REC_THREADS + tid;
        const int nthr = NCTA_REC * REC_THREADS;
        unsigned long long* hp4 = reinterpret_cast<unsigned long long*>(g_hp);
        for (int i = gt; i < NDIR*B_*H_/4; i += nthr) hp4[i] = 0ull;
        for (int i = gt; i < NDIR*CTAS_DIR*32; i += nthr) g_flag[i] = 0u;
    }
    __threadfence();
    __syncthreads();
    if (tid == 0) {
        volatile unsigned* gp = &g_ibg;
        unsigned old = *gp;
        __threadfence();
        if (atomicAdd(&g_ibc, 1u) == NCTA_REC - 1) {
            atomicExch(&g_ibc, 0u); __threadfence(); *gp = old + 1;
        } else { while (*gp == old) {} }
    }
    __syncthreads();

    // warp tiling (16 warps): mi = wid&1 (m16 tile), ni = wid>>1 (n16 group 0..7)
    const int mi = wid & 1;
    const int ni = wid >> 1;
    const int lrow = lane & 15;
    const int lkb  = (lane >> 4) * 16;

    const unsigned a_base = sb + SO_W + (mi*16 + lrow) * 1024;
    const int      a_xor  = ((mi*16 + lrow) & 7) << 4;
    const unsigned b_base = sb + SO_H + (ni*16 + lrow) * 1024;
    const int      b_xor  = ((ni*16 + lrow) & 7) << 4;

    // gating thread mapping: (b, 2 units)
    const int gb = tid & 127;
    const int uh = tid >> 7;           // 0..3 -> units uh*2, uh*2+1
    float hreg[2] = {0.f, 0.f};

    float bhv[2][3];
    #pragma unroll
    for (int q = 0; q < 2; q++)
        #pragma unroll
        for (int gate = 0; gate < 3; gate++)
            bhv[q][gate] = bh[gate*H_ + j0 + uh*2 + q];

    // prefetch xg for t=0
    float xgn[6];
    {
        const int te0 = dir ? (T_ - 1) : 0;
        #pragma unroll
        for (int q = 0; q < 2; q++)
            #pragma unroll
            for (int gate = 0; gate < 3; gate++)
                xgn[q*3 + gate] = __ldcg(&g_xpT[((size_t)te0 * GT + dir*G3
                                        + gate*H_ + j0 + uh*2 + q) * B_ + gb]);
    }

    const __half* hsrc = &g_hp[(size_t)(dir*B_) * H_];
    volatile unsigned* myflag  = &g_flag[(dir*CTAS_DIR + c64) * 32];
    volatile unsigned* pollflg = (tid < CTAS_DIR)
        ? &g_flag[(dir*CTAS_DIR + tid) * 32] : (volatile unsigned*)0;

    for (int t = 0; t < T_; t++) {
        // ---- stage full h of this dir via cp.async (one batch)
        #pragma unroll
        for (int i = 0; i < 16; i++) {
            int idx = tid + i * REC_THREADS;      // 0..8191
            int b = idx >> 6, kq = idx & 63;
            cp16(sb + SO_H + sw_off(b, kq*16), hsrc + (size_t)b * H_ + kq*8);
        }
        CP_WAIT_ALL();
        __syncthreads();

        // ---- HMMA mainloop, K=512 (32 k-steps), warp owns m16 x n16
        float d[2][4];
        #pragma unroll
        for (int g8 = 0; g8 < 2; g8++)
            #pragma unroll
            for (int q = 0; q < 4; q++) d[g8][q] = 0.f;

        #pragma unroll
        for (int ks = 0; ks < 32; ks++) {
            const int kb = ks * 32 + lkb;
            unsigned a[4], bb4[4];
            ldsm4(a,   a_base + (kb ^ a_xor));
            ldsm4(bb4, b_base + (kb ^ b_xor));
            mma16816(d[0], a, bb4[0], bb4[2]);
            mma16816(d[1], a, bb4[1], bb4[3]);
        }

        // ---- epilogue: fragments -> S[32][128] fp32
        {
            const int r0 = mi*16 + (lane >> 2);
            const int c0 = (lane & 3) * 2;
            #pragma unroll
            for (int g8 = 0; g8 < 2; g8++) {
                int col = ni*16 + g8*8 + c0;
                *reinterpret_cast<float2*>(&S[r0 * 128 + col]) =
                    make_float2(d[g8][0], d[g8][1]);
                *reinterpret_cast<float2*>(&S[(r0 + 8) * 128 + col]) =
                    make_float2(d[g8][2], d[g8][3]);
            }
        }
        __syncthreads();

        // ---- gating: thread owns units uh*2, uh*2+1 for batch gb
        __half hnew16[2];
        #pragma unroll
        for (int q = 0; q < 2; q++) {
            int u = uh*2 + q;
            float hg[3];
            #pragma unroll
            for (int gate = 0; gate < 3; gate++)
                hg[gate] = S[(gate*8 + u) * 128 + gb] + bhv[q][gate];
            float r = 1.f / (1.f + __expf(-(xgn[q*3+0] + hg[0])));
            float z = 1.f / (1.f + __expf(-(xgn[q*3+1] + hg[1])));
            float n = tanhf(xgn[q*3+2] + r * hg[2]);
            float hnew = (1.f - z) * n + z * hreg[q];
            hreg[q] = hnew;
            hnew16[q] = __float2half_rn(hnew);
        }
        __stcg(reinterpret_cast<unsigned*>(
                   &g_hp[(size_t)(dir*B_ + gb) * H_ + j0 + uh*2]),
               *reinterpret_cast<unsigned*>(hnew16));

        // ---- flag-array barrier: arrive (1 store), poll 64 flags in parallel
        __syncthreads();                 // all h stores issued (CTA-wide)
        if (tid == 0) {
            __threadfence();             // make h stores GPU-visible (cumulative)
            *myflag = (unsigned)(t + 1); // arrival
        }
        // overlap: prefetch xg for t+1 while other CTAs arrive
        if (t + 1 < T_) {
            const int ten = dir ? (T_ - 2 - t) : (t + 1);
            #pragma unroll
            for (int q = 0; q < 2; q++)
                #pragma unroll
                for (int gate = 0; gate < 3; gate++)
                    xgn[q*3 + gate] = __ldcg(&g_xpT[((size_t)ten * GT + dir*G3
                                            + gate*H_ + j0 + uh*2 + q) * B_ + gb]);
        }
        if (tid < CTAS_DIR) {
            while (*pollflg < (unsigned)(t + 1)) {}
        }
        __syncthreads();
    }

    // final h fp32 for fc
    #pragma unroll
    for (int q = 0; q < 2; q++)
        g_hf[(size_t)(dir*H_ + j0 + uh*2 + q) * B_ + gb] = hreg[q];
}

// =================================================================================
// Phase 3: final FC + sigmoid
// =================================================================================
__global__ void fc_kernel(const float* __restrict__ fcw,
                          const float* __restrict__ fcb,
                          float* __restrict__ out)
{
    int b = threadIdx.x;   // 128 threads
    float s = 0.f;
    for (int j = 0; j < H_; j++)
        s = fmaf(g_hf[(0*H_ + j) * B_ + b], fcw[j], s);
    for (int j = 0; j < H_; j++)
        s = fmaf(g_hf[(1*H_ + j) * B_ + b], fcw[H_ + j], s);
    out[b] = 1.f / (1.f + __expf(-(s + fcb[0])));
}

// =================================================================================
extern "C" void kernel_launch(void* const* d_in, const int* in_sizes, int n_in,
                              void* d_out, int out_size)
{
    const int*   inputs = (const int*)  d_in[0];
    const float* emb    = (const float*)d_in[1];
    const float* Wihf   = (const float*)d_in[2];
    const float* Whhf   = (const float*)d_in[3];
    const float* bihf   = (const float*)d_in[4];
    const float* bhhf   = (const float*)d_in[5];
    const float* Wihb   = (const float*)d_in[6];
    const float* Whhb   = (const float*)d_in[7];
    const float* bihb   = (const float*)d_in[8];
    const float* bhhb   = (const float*)d_in[9];
    const float* fcw    = (const float*)d_in[10];
    const float* fcb    = (const float*)d_in[11];
    float* out = (float*)d_out;

    cudaFuncSetAttribute(proj_kernel,
                         cudaFuncAttributeMaxDynamicSharedMemorySize, PJ_END);
    cudaFuncSetAttribute(rec_kernel,
                         cudaFuncAttributeMaxDynamicSharedMemorySize, SO_END);

    // 2 dummies: puts rec_kernel at ncu capture index 5
    dummy_kernel<<<1, 32>>>();
    dummy_kernel<<<1, 32>>>();

    proj_kernel<<<dim3(24, 32), 256, PJ_END>>>(inputs, emb, Wihf, Wihb, bihf, bihb);
    rec_kernel<<<NCTA_REC, REC_THREADS, SO_END>>>(Whhf, Whhb, bhhf, bhhb);
    fc_kernel<<<1, B_>>>(fcw, fcb, out);

    (void)in_sizes; (void)n_in; (void)out_size;
}